// round 15
// baseline (speedup 1.0000x reference)
#include <cuda_runtime.h>
#include <cuda_fp16.h>
#include <cstdint>

// ---------------- problem constants ----------------
#define M_TOTAL 8192
#define N_TOTAL 4096
#define K_IN    4096

#define BM 128
#define BN 128
#define BKS 64                        // fp16 k-elems per stage
#define NK (K_IN / BKS)               // 64
#define STAGES 3
#define PITCH 72                      // smem row pitch in fp16 (64 data + 8 pad)
#define TILE_BYTES (128 * PITCH * 2)  // 18432 B per (A or B) stage tile
#define STAGE_BYTES (2 * TILE_BYTES)  // 36864
#define SMEM_BYTES (STAGES * STAGE_BYTES)  // 110592 (x2 CTAs = 221KB < 228KB)

#define TAU 0.125f
#define LCAP 1024

#define NX8 ((size_t)M_TOTAL * K_IN / 8)   // x 8-elem chunks: 4.19M
#define NW8 ((size_t)N_TOTAL * K_IN / 8)   // w 8-elem chunks: 2.10M

// ---------------- scratch ----------------
__device__ __half g_A[(size_t)M_TOTAL * K_IN];  // hi limb: fl16(x)
__device__ __half g_W[(size_t)N_TOTAL * K_IN];  // sign(W) as fp16

// ---------------- helpers ----------------
static __device__ __forceinline__ void cpa16(uint32_t dst, const void* src) {
    asm volatile("cp.async.cg.shared.global [%0], [%1], 16;" :: "r"(dst), "l"(src));
}
static __device__ __forceinline__ void ldsm4(uint32_t* r, uint32_t addr) {
    asm volatile("ldmatrix.sync.aligned.m8n8.x4.shared.b16 {%0,%1,%2,%3}, [%4];"
                 : "=r"(r[0]), "=r"(r[1]), "=r"(r[2]), "=r"(r[3]) : "r"(addr));
}
static __device__ __forceinline__ void mma16816(float* c, const uint32_t* a, const uint32_t* b) {
    asm volatile(
        "mma.sync.aligned.m16n8k16.row.col.f32.f16.f16.f32 "
        "{%0,%1,%2,%3}, {%4,%5,%6,%7}, {%8,%9}, {%0,%1,%2,%3};"
        : "+f"(c[0]), "+f"(c[1]), "+f"(c[2]), "+f"(c[3])
        : "r"(a[0]), "r"(a[1]), "r"(a[2]), "r"(a[3]), "r"(b[0]), "r"(b[1]));
}
static __device__ __forceinline__ float sgnf(float z) {
    return (z > 0.f) ? 1.f : ((z < 0.f) ? -1.f : 0.f);
}

// ---------------- register-isolated fixup (ABI call keeps mainloop regalloc clean) ----
__device__ __noinline__ void fixup_item(const float* __restrict__ x,
                                        float* __restrict__ out,
                                        unsigned idx, float zhi, int lane) {
    const int m = idx >> 12;
    const int n = idx & (N_TOTAL - 1);
    const float4* xr = reinterpret_cast<const float4*>(x + (size_t)m * K_IN);
    const uint4*  wr = reinterpret_cast<const uint4*>(g_W + (size_t)n * K_IN);
    float s = 0.f;
    #pragma unroll 4
    for (int i = 0; i < 16; i++) {
        const int ch = i * 32 + lane;        // chunk of 8 elems
        float4 x0 = xr[2 * ch];
        float4 x1 = xr[2 * ch + 1];
        uint4  wv = wr[ch];
        const __half2* wh = reinterpret_cast<const __half2*>(&wv);
        float xs[8] = {x0.x, x0.y, x0.z, x0.w, x1.x, x1.y, x1.z, x1.w};
        #pragma unroll
        for (int q = 0; q < 4; q++) {
            float2 wf = __half22float2(wh[q]);
            float xa = xs[2 * q], xb = xs[2 * q + 1];
            float la = xa - __half2float(__float2half_rn(xa));
            float lb = xb - __half2float(__float2half_rn(xb));
            s += la * wf.x + lb * wf.y;
        }
    }
    #pragma unroll
    for (int o = 16; o; o >>= 1) s += __shfl_xor_sync(0xffffffffu, s, o);
    if (lane == 0) out[idx] = sgnf(zhi + s);
}

// ---------------- merged prep kernel: 8 elems/thread, hi + sign only ----------------
__global__ void prep_all(const float* __restrict__ x, const float* __restrict__ w) {
    const size_t i = (size_t)blockIdx.x * blockDim.x + threadIdx.x;
    if (i < NX8) {
        float4 v0 = reinterpret_cast<const float4*>(x)[2 * i];
        float4 v1 = reinterpret_cast<const float4*>(x)[2 * i + 1];
        float vv[8] = {v0.x, v0.y, v0.z, v0.w, v1.x, v1.y, v1.z, v1.w};
        __half hi[8];
        #pragma unroll
        for (int j = 0; j < 8; j++) hi[j] = __float2half_rn(vv[j]);
        reinterpret_cast<uint4*>(g_A)[i] = *reinterpret_cast<uint4*>(hi);
    } else {
        const size_t k = i - NX8;
        if (k < NW8) {
            float4 v0 = reinterpret_cast<const float4*>(w)[2 * k];
            float4 v1 = reinterpret_cast<const float4*>(w)[2 * k + 1];
            float vv[8] = {v0.x, v0.y, v0.z, v0.w, v1.x, v1.y, v1.z, v1.w};
            __half s[8];
            #pragma unroll
            for (int j = 0; j < 8; j++) s[j] = __float2half_rn(sgnf(vv[j]));
            reinterpret_cast<uint4*>(g_W)[k] = *reinterpret_cast<uint4*>(s);
        }
    }
}

// ---------------- GEMM kernel (R11/R14 mainloop verbatim) ----------------
__global__ void __launch_bounds__(256, 2)
binlin_gemm(const float* __restrict__ x, const float* __restrict__ bias,
            float* __restrict__ out) {
    extern __shared__ __align__(16) char smem[];
    const uint32_t su = (uint32_t)__cvta_generic_to_shared(smem);

    const int tid  = threadIdx.x;
    const int wid  = tid >> 5;
    const int lane = tid & 31;
    const int wm = (wid >> 1) * 32;
    const int wn = (wid & 1) * 64;

    const int m_base = blockIdx.y * BM;
    const int n_base = blockIdx.x * BN;

    float acc[2][8][4];
    #pragma unroll
    for (int mi = 0; mi < 2; mi++)
        #pragma unroll
        for (int ni = 0; ni < 8; ni++)
            #pragma unroll
            for (int j = 0; j < 4; j++) acc[mi][ni][j] = 0.f;

    const int a_row_off = (lane & 7) + ((lane >> 3) & 1) * 8;
    const int a_col_off = (lane >> 4) * 8;
    const int b_row_off = (lane & 7) + (lane >> 4) * 8;
    const int b_col_off = ((lane >> 3) & 1) * 8;

    auto load_chunk = [&](int s, int kk, int i) {
        const uint32_t abase = su + s * STAGE_BYTES;
        const uint32_t bbase = abase + TILE_BYTES;
        const int ka = kk * BKS;
        const int cid = tid + i * 256;
        const int row = cid >> 3;
        const int c   = cid & 7;
        cpa16(abase + row * (PITCH * 2) + c * 16,
              &g_A[(size_t)(m_base + row) * K_IN + ka + c * 8]);
        cpa16(bbase + row * (PITCH * 2) + c * 16,
              &g_W[(size_t)(n_base + row) * K_IN + ka + c * 8]);
    };
    auto load_stage = [&](int s, int kk) {
        #pragma unroll
        for (int i = 0; i < 4; i++) load_chunk(s, kk, i);
    };

    auto ldsm_ks = [&](int s, int ks, uint32_t a[2][4], uint32_t b[8][2]) {
        const uint32_t abase = su + s * STAGE_BYTES;
        const uint32_t bbase = abase + TILE_BYTES;
        #pragma unroll
        for (int mi = 0; mi < 2; mi++) {
            uint32_t addr = abase +
                ((wm + mi * 16 + a_row_off) * PITCH + ks * 16 + a_col_off) * 2;
            ldsm4(a[mi], addr);
        }
        #pragma unroll
        for (int p = 0; p < 4; p++) {
            uint32_t t[4];
            uint32_t addr = bbase +
                ((wn + p * 16 + b_row_off) * PITCH + ks * 16 + b_col_off) * 2;
            ldsm4(t, addr);
            b[2 * p + 0][0] = t[0]; b[2 * p + 0][1] = t[1];
            b[2 * p + 1][0] = t[2]; b[2 * p + 1][1] = t[3];
        }
    };
    auto mma_all = [&](uint32_t a[2][4], uint32_t b[8][2]) {
        #pragma unroll
        for (int mi = 0; mi < 2; mi++)
            #pragma unroll
            for (int ni = 0; ni < 8; ni++)
                mma16816(acc[mi][ni], a[mi], b[ni]);
    };

    auto step = [&](int kk, int sc, int sl) {
        asm volatile("cp.async.wait_group %0;" :: "n"(STAGES - 2));
        __syncthreads();
        const bool ld = (kk + STAGES - 1 < NK);
        uint32_t a0[2][4], b0[8][2], a1[2][4], b1[8][2];
        ldsm_ks(sc, 0, a0, b0);
        if (ld) load_chunk(sl, kk + STAGES - 1, 0);
        ldsm_ks(sc, 1, a1, b1);
        mma_all(a0, b0);
        if (ld) load_chunk(sl, kk + STAGES - 1, 1);
        ldsm_ks(sc, 2, a0, b0);
        mma_all(a1, b1);
        if (ld) load_chunk(sl, kk + STAGES - 1, 2);
        ldsm_ks(sc, 3, a1, b1);
        mma_all(a0, b0);
        if (ld) load_chunk(sl, kk + STAGES - 1, 3);
        asm volatile("cp.async.commit_group;");
        mma_all(a1, b1);
    };

    // ---- prologue ----
    #pragma unroll
    for (int s = 0; s < STAGES - 1; s++) {
        load_stage(s, s);
        asm volatile("cp.async.commit_group;");
    }

    // ---- mainloop: unrolled by the stage period (3) ----
    for (int kt = 0; kt < 21; kt++) {
        const int kk = kt * 3;
        step(kk + 0, 0, 2);
        step(kk + 1, 1, 0);
        step(kk + 2, 2, 1);
    }
    step(63, 0, 2);   // tail (63 % 3 == 0)

    // ---- per-CTA worklist in smem ----
    unsigned* s_cnt = reinterpret_cast<unsigned*>(smem);
    unsigned* s_idx = reinterpret_cast<unsigned*>(smem + 16);
    float*    s_z   = reinterpret_cast<float*>(smem + 16 + LCAP * 4);
    __syncthreads();
    if (tid == 0) *s_cnt = 0u;
    __syncthreads();

    // ---- epilogue: provisional sign + flag near-zero outputs ----
    #pragma unroll
    for (int mi = 0; mi < 2; mi++) {
        #pragma unroll
        for (int ni = 0; ni < 8; ni++) {
            const int r = m_base + wm + mi * 16 + (lane >> 2);
            const int c = n_base + wn + ni * 8 + (lane & 3) * 2;
            const float b0 = bias[c];
            const float b1 = bias[c + 1];
            float z[4];
            z[0] = acc[mi][ni][0] + b0;
            z[1] = acc[mi][ni][1] + b1;
            z[2] = acc[mi][ni][2] + b0;
            z[3] = acc[mi][ni][3] + b1;
            float2 v0, v1;
            v0.x = sgnf(z[0]); v0.y = sgnf(z[1]);
            v1.x = sgnf(z[2]); v1.y = sgnf(z[3]);
            *reinterpret_cast<float2*>(&out[(size_t)r * N_TOTAL + c]) = v0;
            *reinterpret_cast<float2*>(&out[(size_t)(r + 8) * N_TOTAL + c]) = v1;
            #pragma unroll
            for (int j = 0; j < 4; j++) {
                if (fabsf(z[j]) < TAU) {
                    const int rr = r + (j >> 1) * 8;
                    const int cc = c + (j & 1);
                    unsigned p = atomicAdd(s_cnt, 1u);
                    if (p < LCAP) {
                        s_idx[p] = (unsigned)rr * N_TOTAL + cc;
                        s_z[p]   = z[j];
                    }
                }
            }
        }
    }
    __syncthreads();

    // ---- inline dispatch, register-isolated body ----
    const unsigned total = min(*s_cnt, (unsigned)LCAP);
    for (unsigned it = wid; it < total; it += 8) {
        fixup_item(x, out, s_idx[it], s_z[it], lane);
    }
}

// ---------------- host launch ----------------
extern "C" void kernel_launch(void* const* d_in, const int* in_sizes, int n_in,
                              void* d_out, int out_size) {
    const float* x    = (const float*)d_in[0];
    const float* w    = (const float*)d_in[1];
    const float* bias = (const float*)d_in[2];
    float* out = (float*)d_out;

    const int nv = (int)((NX8 + NW8 + 255) / 256);
    prep_all<<<nv, 256>>>(x, w);

    cudaFuncSetAttribute(binlin_gemm, cudaFuncAttributeMaxDynamicSharedMemorySize,
                         SMEM_BYTES);
    binlin_gemm<<<dim3(N_TOTAL / BN, M_TOTAL / BM), 256, SMEM_BYTES>>>(x, bias, out);
}

// round 16
// speedup vs baseline: 1.0532x; 1.0532x over previous
#include <cuda_runtime.h>
#include <cuda_fp16.h>
#include <cstdint>

// ---------------- problem constants ----------------
#define M_TOTAL 8192
#define N_TOTAL 4096
#define K_IN    4096

#define BM 128
#define BN 128
#define BKS 64                        // fp16 k-elems per stage
#define NK (K_IN / BKS)               // 64
#define STAGES 3
#define PITCH 72                      // smem row pitch in fp16 (64 data + 8 pad)
#define TILE_BYTES (128 * PITCH * 2)  // 18432 B per (A or B) stage tile
#define STAGE_BYTES (2 * TILE_BYTES)  // 36864
#define SMEM_BYTES (STAGES * STAGE_BYTES)  // 110592 (x2 CTAs = 221KB < 228KB)

#define TAU 0.125f
#define LCAP 1024

#define NX8 ((size_t)M_TOTAL * K_IN / 8)   // x 8-elem chunks: 4.19M
#define NW8 ((size_t)N_TOTAL * K_IN / 8)   // w 8-elem chunks: 2.10M

// ---------------- scratch ----------------
__device__ __half g_A[(size_t)M_TOTAL * K_IN];  // hi limb: fl16(x)
__device__ __half g_L[(size_t)M_TOTAL * K_IN];  // lo limb: fl16(x - hi)
__device__ __half g_W[(size_t)N_TOTAL * K_IN];  // sign(W) as fp16

// ---------------- helpers ----------------
static __device__ __forceinline__ void cpa16(uint32_t dst, const void* src) {
    asm volatile("cp.async.cg.shared.global [%0], [%1], 16;" :: "r"(dst), "l"(src));
}
static __device__ __forceinline__ void ldsm4(uint32_t* r, uint32_t addr) {
    asm volatile("ldmatrix.sync.aligned.m8n8.x4.shared.b16 {%0,%1,%2,%3}, [%4];"
                 : "=r"(r[0]), "=r"(r[1]), "=r"(r[2]), "=r"(r[3]) : "r"(addr));
}
static __device__ __forceinline__ void mma16816(float* c, const uint32_t* a, const uint32_t* b) {
    asm volatile(
        "mma.sync.aligned.m16n8k16.row.col.f32.f16.f16.f32 "
        "{%0,%1,%2,%3}, {%4,%5,%6,%7}, {%8,%9}, {%0,%1,%2,%3};"
        : "+f"(c[0]), "+f"(c[1]), "+f"(c[2]), "+f"(c[3])
        : "r"(a[0]), "r"(a[1]), "r"(a[2]), "r"(a[3]), "r"(b[0]), "r"(b[1]));
}
static __device__ __forceinline__ float sgnf(float z) {
    return (z > 0.f) ? 1.f : ((z < 0.f) ? -1.f : 0.f);
}

// ---------------- merged prep kernel: 8 elems/thread, writes hi/lo/sign ----------------
__global__ void prep_all(const float* __restrict__ x, const float* __restrict__ w) {
    const size_t i = (size_t)blockIdx.x * blockDim.x + threadIdx.x;
    if (i < NX8) {
        float4 v0 = reinterpret_cast<const float4*>(x)[2 * i];
        float4 v1 = reinterpret_cast<const float4*>(x)[2 * i + 1];
        float vv[8] = {v0.x, v0.y, v0.z, v0.w, v1.x, v1.y, v1.z, v1.w};
        __half hi[8], lo[8];
        #pragma unroll
        for (int j = 0; j < 8; j++) {
            hi[j] = __float2half_rn(vv[j]);
            lo[j] = __float2half_rn(vv[j] - __half2float(hi[j]));
        }
        reinterpret_cast<uint4*>(g_A)[i] = *reinterpret_cast<uint4*>(hi);
        reinterpret_cast<uint4*>(g_L)[i] = *reinterpret_cast<uint4*>(lo);
    } else {
        const size_t k = i - NX8;
        if (k < NW8) {
            float4 v0 = reinterpret_cast<const float4*>(w)[2 * k];
            float4 v1 = reinterpret_cast<const float4*>(w)[2 * k + 1];
            float vv[8] = {v0.x, v0.y, v0.z, v0.w, v1.x, v1.y, v1.z, v1.w};
            __half s[8];
            #pragma unroll
            for (int j = 0; j < 8; j++) s[j] = __float2half_rn(sgnf(vv[j]));
            reinterpret_cast<uint4*>(g_W)[k] = *reinterpret_cast<uint4*>(s);
        }
    }
}

// ---------------- GEMM kernel (128x128, 256 thr, 2 CTAs/SM) ----------------
__global__ void __launch_bounds__(256, 2)
binlin_gemm(const float* __restrict__ bias, float* __restrict__ out) {
    extern __shared__ __align__(16) char smem[];
    const uint32_t su = (uint32_t)__cvta_generic_to_shared(smem);

    const int tid  = threadIdx.x;
    const int wid  = tid >> 5;
    const int lane = tid & 31;
    const int wm = (wid >> 1) * 32;
    const int wn = (wid & 1) * 64;

    const int m_base = blockIdx.y * BM;
    const int n_base = blockIdx.x * BN;

    float acc[2][8][4];
    #pragma unroll
    for (int mi = 0; mi < 2; mi++)
        #pragma unroll
        for (int ni = 0; ni < 8; ni++)
            #pragma unroll
            for (int j = 0; j < 4; j++) acc[mi][ni][j] = 0.f;

    const int a_row_off = (lane & 7) + ((lane >> 3) & 1) * 8;
    const int a_col_off = (lane >> 4) * 8;
    const int b_row_off = (lane & 7) + (lane >> 4) * 8;
    const int b_col_off = ((lane >> 3) & 1) * 8;

    auto load_chunk = [&](int s, int kk, int i) {
        const uint32_t abase = su + s * STAGE_BYTES;
        const uint32_t bbase = abase + TILE_BYTES;
        const int ka = kk * BKS;
        const int cid = tid + i * 256;
        const int row = cid >> 3;
        const int c   = cid & 7;
        cpa16(abase + row * (PITCH * 2) + c * 16,
              &g_A[(size_t)(m_base + row) * K_IN + ka + c * 8]);
        cpa16(bbase + row * (PITCH * 2) + c * 16,
              &g_W[(size_t)(n_base + row) * K_IN + ka + c * 8]);
    };
    auto load_stage = [&](int s, int kk) {
        #pragma unroll
        for (int i = 0; i < 4; i++) load_chunk(s, kk, i);
    };

    auto ldsm_ks = [&](int s, int ks, uint32_t a[2][4], uint32_t b[8][2]) {
        const uint32_t abase = su + s * STAGE_BYTES;
        const uint32_t bbase = abase + TILE_BYTES;
        #pragma unroll
        for (int mi = 0; mi < 2; mi++) {
            uint32_t addr = abase +
                ((wm + mi * 16 + a_row_off) * PITCH + ks * 16 + a_col_off) * 2;
            ldsm4(a[mi], addr);
        }
        #pragma unroll
        for (int p = 0; p < 4; p++) {
            uint32_t t[4];
            uint32_t addr = bbase +
                ((wn + p * 16 + b_row_off) * PITCH + ks * 16 + b_col_off) * 2;
            ldsm4(t, addr);
            b[2 * p + 0][0] = t[0]; b[2 * p + 0][1] = t[1];
            b[2 * p + 1][0] = t[2]; b[2 * p + 1][1] = t[3];
        }
    };
    auto mma_all = [&](uint32_t a[2][4], uint32_t b[8][2]) {
        #pragma unroll
        for (int mi = 0; mi < 2; mi++)
            #pragma unroll
            for (int ni = 0; ni < 8; ni++)
                mma16816(acc[mi][ni], a[mi], b[ni]);
    };

    auto step = [&](int kk, int sc, int sl) {
        asm volatile("cp.async.wait_group %0;" :: "n"(STAGES - 2));
        __syncthreads();
        const bool ld = (kk + STAGES - 1 < NK);
        uint32_t a0[2][4], b0[8][2], a1[2][4], b1[8][2];
        ldsm_ks(sc, 0, a0, b0);
        if (ld) load_chunk(sl, kk + STAGES - 1, 0);
        ldsm_ks(sc, 1, a1, b1);
        mma_all(a0, b0);
        if (ld) load_chunk(sl, kk + STAGES - 1, 1);
        ldsm_ks(sc, 2, a0, b0);
        mma_all(a1, b1);
        if (ld) load_chunk(sl, kk + STAGES - 1, 2);
        ldsm_ks(sc, 3, a1, b1);
        mma_all(a0, b0);
        if (ld) load_chunk(sl, kk + STAGES - 1, 3);
        asm volatile("cp.async.commit_group;");
        mma_all(a1, b1);
    };

    // ---- prologue ----
    #pragma unroll
    for (int s = 0; s < STAGES - 1; s++) {
        load_stage(s, s);
        asm volatile("cp.async.commit_group;");
    }

    // ---- mainloop: unrolled by the stage period (3) ----
    for (int kt = 0; kt < 21; kt++) {
        const int kk = kt * 3;
        step(kk + 0, 0, 2);
        step(kk + 1, 1, 0);
        step(kk + 2, 2, 1);
    }
    step(63, 0, 2);   // tail (63 % 3 == 0)

    // ---- per-CTA worklist in smem ----
    unsigned* s_cnt = reinterpret_cast<unsigned*>(smem);
    unsigned* s_idx = reinterpret_cast<unsigned*>(smem + 16);
    float*    s_z   = reinterpret_cast<float*>(smem + 16 + LCAP * 4);
    __syncthreads();
    if (tid == 0) *s_cnt = 0u;
    __syncthreads();

    // ---- epilogue: provisional sign + flag near-zero outputs ----
    #pragma unroll
    for (int mi = 0; mi < 2; mi++) {
        #pragma unroll
        for (int ni = 0; ni < 8; ni++) {
            const int r = m_base + wm + mi * 16 + (lane >> 2);
            const int c = n_base + wn + ni * 8 + (lane & 3) * 2;
            const float b0 = bias[c];
            const float b1 = bias[c + 1];
            float z[4];
            z[0] = acc[mi][ni][0] + b0;
            z[1] = acc[mi][ni][1] + b1;
            z[2] = acc[mi][ni][2] + b0;
            z[3] = acc[mi][ni][3] + b1;
            float2 v0, v1;
            v0.x = sgnf(z[0]); v0.y = sgnf(z[1]);
            v1.x = sgnf(z[2]); v1.y = sgnf(z[3]);
            *reinterpret_cast<float2*>(&out[(size_t)r * N_TOTAL + c]) = v0;
            *reinterpret_cast<float2*>(&out[(size_t)(r + 8) * N_TOTAL + c]) = v1;
            #pragma unroll
            for (int j = 0; j < 4; j++) {
                if (fabsf(z[j]) < TAU) {
                    const int rr = r + (j >> 1) * 8;
                    const int cc = c + (j & 1);
                    unsigned p = atomicAdd(s_cnt, 1u);
                    if (p < LCAP) {
                        s_idx[p] = (unsigned)rr * N_TOTAL + cc;
                        s_z[p]   = z[j];
                    }
                }
            }
        }
    }
    __syncthreads();

    // ---- inline fixup: warp-per-item exact lo-limb correction (from g_L) ----
    const unsigned total = min(*s_cnt, (unsigned)LCAP);
    for (unsigned it = wid; it < total; it += 8) {
        const unsigned idx = s_idx[it];
        const int m = idx >> 12;
        const int n = idx & (N_TOTAL - 1);
        const uint4* lr = reinterpret_cast<const uint4*>(g_L + (size_t)m * K_IN);
        const uint4* wr = reinterpret_cast<const uint4*>(g_W + (size_t)n * K_IN);
        float s = 0.f;
        #pragma unroll 4
        for (int i = 0; i < 16; i++) {
            const int ch = i * 32 + lane;
            uint4 lv = lr[ch];
            uint4 wv = wr[ch];
            const __half2* lh = reinterpret_cast<const __half2*>(&lv);
            const __half2* wh = reinterpret_cast<const __half2*>(&wv);
            #pragma unroll
            for (int q = 0; q < 4; q++) {
                float2 lf = __half22float2(lh[q]);
                float2 wf = __half22float2(wh[q]);
                s += lf.x * wf.x + lf.y * wf.y;
            }
        }
        #pragma unroll
        for (int o = 16; o; o >>= 1) s += __shfl_xor_sync(0xffffffffu, s, o);
        if (lane == 0) out[idx] = sgnf(s_z[it] + s);
    }
}

// ---------------- host launch ----------------
extern "C" void kernel_launch(void* const* d_in, const int* in_sizes, int n_in,
                              void* d_out, int out_size) {
    const float* x    = (const float*)d_in[0];
    const float* w    = (const float*)d_in[1];
    const float* bias = (const float*)d_in[2];
    float* out = (float*)d_out;

    const int nv = (int)((NX8 + NW8 + 255) / 256);
    prep_all<<<nv, 256>>>(x, w);

    cudaFuncSetAttribute(binlin_gemm, cudaFuncAttributeMaxDynamicSharedMemorySize,
                         SMEM_BYTES);
    binlin_gemm<<<dim3(N_TOTAL / BN, M_TOTAL / BM), 256, SMEM_BYTES>>>(bias, out);
}

// round 17
// speedup vs baseline: 1.0769x; 1.0225x over previous
#include <cuda_runtime.h>
#include <cuda_fp16.h>
#include <cstdint>

// ---------------- problem constants ----------------
#define M_TOTAL 8192
#define N_TOTAL 4096
#define K_IN    4096

#define BM 128
#define BN 128
#define BKS 64                        // fp16 k-elems per stage
#define NK (K_IN / BKS)               // 64
#define STAGES 3
#define PITCH 72                      // smem row pitch in fp16 (64 data + 8 pad)
#define TILE_BYTES (128 * PITCH * 2)  // 18432 B per (A or B) stage tile
#define STAGE_BYTES (2 * TILE_BYTES)  // 36864
#define SMEM_BYTES (STAGES * STAGE_BYTES)  // 110592 (x2 CTAs = 221KB < 228KB)

#define TAU 0.08f                     // ~9 sigma of the lo-limb correction
#define LCAP 1024

#define NX8 ((size_t)M_TOTAL * K_IN / 8)   // x 8-elem chunks: 4.19M
#define NW8 ((size_t)N_TOTAL * K_IN / 8)   // w 8-elem chunks: 2.10M

// ---------------- scratch ----------------
__device__ __half g_A[(size_t)M_TOTAL * K_IN];  // hi limb: fl16(x)
__device__ __half g_L[(size_t)M_TOTAL * K_IN];  // lo limb: fl16(x - hi)
__device__ __half g_W[(size_t)N_TOTAL * K_IN];  // sign(W) as fp16

// ---------------- helpers ----------------
static __device__ __forceinline__ void cpa16(uint32_t dst, const void* src) {
    asm volatile("cp.async.cg.shared.global [%0], [%1], 16;" :: "r"(dst), "l"(src));
}
static __device__ __forceinline__ void ldsm4(uint32_t* r, uint32_t addr) {
    asm volatile("ldmatrix.sync.aligned.m8n8.x4.shared.b16 {%0,%1,%2,%3}, [%4];"
                 : "=r"(r[0]), "=r"(r[1]), "=r"(r[2]), "=r"(r[3]) : "r"(addr));
}
static __device__ __forceinline__ void mma16816(float* c, const uint32_t* a, const uint32_t* b) {
    asm volatile(
        "mma.sync.aligned.m16n8k16.row.col.f32.f16.f16.f32 "
        "{%0,%1,%2,%3}, {%4,%5,%6,%7}, {%8,%9}, {%0,%1,%2,%3};"
        : "+f"(c[0]), "+f"(c[1]), "+f"(c[2]), "+f"(c[3])
        : "r"(a[0]), "r"(a[1]), "r"(a[2]), "r"(a[3]), "r"(b[0]), "r"(b[1]));
}
static __device__ __forceinline__ float sgnf(float z) {
    return (z > 0.f) ? 1.f : ((z < 0.f) ? -1.f : 0.f);
}

// ---------------- merged prep kernel: 8 elems/thread, writes hi/lo/sign ----------------
__global__ void prep_all(const float* __restrict__ x, const float* __restrict__ w) {
    const size_t i = (size_t)blockIdx.x * blockDim.x + threadIdx.x;
    if (i < NX8) {
        float4 v0 = reinterpret_cast<const float4*>(x)[2 * i];
        float4 v1 = reinterpret_cast<const float4*>(x)[2 * i + 1];
        float vv[8] = {v0.x, v0.y, v0.z, v0.w, v1.x, v1.y, v1.z, v1.w};
        __half hi[8], lo[8];
        #pragma unroll
        for (int j = 0; j < 8; j++) {
            hi[j] = __float2half_rn(vv[j]);
            lo[j] = __float2half_rn(vv[j] - __half2float(hi[j]));
        }
        reinterpret_cast<uint4*>(g_A)[i] = *reinterpret_cast<uint4*>(hi);
        reinterpret_cast<uint4*>(g_L)[i] = *reinterpret_cast<uint4*>(lo);
    } else {
        const size_t k = i - NX8;
        if (k < NW8) {
            float4 v0 = reinterpret_cast<const float4*>(w)[2 * k];
            float4 v1 = reinterpret_cast<const float4*>(w)[2 * k + 1];
            float vv[8] = {v0.x, v0.y, v0.z, v0.w, v1.x, v1.y, v1.z, v1.w};
            __half s[8];
            #pragma unroll
            for (int j = 0; j < 8; j++) s[j] = __float2half_rn(sgnf(vv[j]));
            reinterpret_cast<uint4*>(g_W)[k] = *reinterpret_cast<uint4*>(s);
        }
    }
}

// ---------------- GEMM kernel (128x128, 256 thr, 2 CTAs/SM) ----------------
__global__ void __launch_bounds__(256, 2)
binlin_gemm(const float* __restrict__ bias, float* __restrict__ out) {
    extern __shared__ __align__(16) char smem[];
    const uint32_t su = (uint32_t)__cvta_generic_to_shared(smem);

    const int tid  = threadIdx.x;
    const int wid  = tid >> 5;
    const int lane = tid & 31;
    const int wm = (wid >> 1) * 32;
    const int wn = (wid & 1) * 64;

    const int m_base = blockIdx.y * BM;
    const int n_base = blockIdx.x * BN;

    float acc[2][8][4];
    #pragma unroll
    for (int mi = 0; mi < 2; mi++)
        #pragma unroll
        for (int ni = 0; ni < 8; ni++)
            #pragma unroll
            for (int j = 0; j < 4; j++) acc[mi][ni][j] = 0.f;

    const int a_row_off = (lane & 7) + ((lane >> 3) & 1) * 8;
    const int a_col_off = (lane >> 4) * 8;
    const int b_row_off = (lane & 7) + (lane >> 4) * 8;
    const int b_col_off = ((lane >> 3) & 1) * 8;

    auto load_chunk = [&](int s, int kk, int i) {
        const uint32_t abase = su + s * STAGE_BYTES;
        const uint32_t bbase = abase + TILE_BYTES;
        const int ka = kk * BKS;
        const int cid = tid + i * 256;
        const int row = cid >> 3;
        const int c   = cid & 7;
        cpa16(abase + row * (PITCH * 2) + c * 16,
              &g_A[(size_t)(m_base + row) * K_IN + ka + c * 8]);
        cpa16(bbase + row * (PITCH * 2) + c * 16,
              &g_W[(size_t)(n_base + row) * K_IN + ka + c * 8]);
    };
    auto load_stage = [&](int s, int kk) {
        #pragma unroll
        for (int i = 0; i < 4; i++) load_chunk(s, kk, i);
    };

    auto ldsm_ks = [&](int s, int ks, uint32_t a[2][4], uint32_t b[8][2]) {
        const uint32_t abase = su + s * STAGE_BYTES;
        const uint32_t bbase = abase + TILE_BYTES;
        #pragma unroll
        for (int mi = 0; mi < 2; mi++) {
            uint32_t addr = abase +
                ((wm + mi * 16 + a_row_off) * PITCH + ks * 16 + a_col_off) * 2;
            ldsm4(a[mi], addr);
        }
        #pragma unroll
        for (int p = 0; p < 4; p++) {
            uint32_t t[4];
            uint32_t addr = bbase +
                ((wn + p * 16 + b_row_off) * PITCH + ks * 16 + b_col_off) * 2;
            ldsm4(t, addr);
            b[2 * p + 0][0] = t[0]; b[2 * p + 0][1] = t[1];
            b[2 * p + 1][0] = t[2]; b[2 * p + 1][1] = t[3];
        }
    };
    auto mma_all = [&](uint32_t a[2][4], uint32_t b[8][2]) {
        #pragma unroll
        for (int mi = 0; mi < 2; mi++)
            #pragma unroll
            for (int ni = 0; ni < 8; ni++)
                mma16816(acc[mi][ni], a[mi], b[ni]);
    };

    auto step = [&](int kk, int sc, int sl) {
        asm volatile("cp.async.wait_group %0;" :: "n"(STAGES - 2));
        __syncthreads();
        const bool ld = (kk + STAGES - 1 < NK);
        uint32_t a0[2][4], b0[8][2], a1[2][4], b1[8][2];
        ldsm_ks(sc, 0, a0, b0);
        if (ld) load_chunk(sl, kk + STAGES - 1, 0);
        ldsm_ks(sc, 1, a1, b1);
        mma_all(a0, b0);
        if (ld) load_chunk(sl, kk + STAGES - 1, 1);
        ldsm_ks(sc, 2, a0, b0);
        mma_all(a1, b1);
        if (ld) load_chunk(sl, kk + STAGES - 1, 2);
        ldsm_ks(sc, 3, a1, b1);
        mma_all(a0, b0);
        if (ld) load_chunk(sl, kk + STAGES - 1, 3);
        asm volatile("cp.async.commit_group;");
        mma_all(a1, b1);
    };

    // ---- prologue ----
    #pragma unroll
    for (int s = 0; s < STAGES - 1; s++) {
        load_stage(s, s);
        asm volatile("cp.async.commit_group;");
    }

    // ---- mainloop: unrolled by the stage period (3) ----
    for (int kt = 0; kt < 21; kt++) {
        const int kk = kt * 3;
        step(kk + 0, 0, 2);
        step(kk + 1, 1, 0);
        step(kk + 2, 2, 1);
    }
    step(63, 0, 2);   // tail (63 % 3 == 0)

    // ---- per-CTA worklist in smem ----
    unsigned* s_cnt = reinterpret_cast<unsigned*>(smem);
    unsigned* s_idx = reinterpret_cast<unsigned*>(smem + 16);
    float*    s_z   = reinterpret_cast<float*>(smem + 16 + LCAP * 4);
    __syncthreads();
    if (tid == 0) *s_cnt = 0u;
    __syncthreads();

    // ---- epilogue: provisional sign + flag near-zero outputs ----
    #pragma unroll
    for (int mi = 0; mi < 2; mi++) {
        #pragma unroll
        for (int ni = 0; ni < 8; ni++) {
            const int r = m_base + wm + mi * 16 + (lane >> 2);
            const int c = n_base + wn + ni * 8 + (lane & 3) * 2;
            const float b0 = bias[c];
            const float b1 = bias[c + 1];
            float z[4];
            z[0] = acc[mi][ni][0] + b0;
            z[1] = acc[mi][ni][1] + b1;
            z[2] = acc[mi][ni][2] + b0;
            z[3] = acc[mi][ni][3] + b1;
            float2 v0, v1;
            v0.x = sgnf(z[0]); v0.y = sgnf(z[1]);
            v1.x = sgnf(z[2]); v1.y = sgnf(z[3]);
            *reinterpret_cast<float2*>(&out[(size_t)r * N_TOTAL + c]) = v0;
            *reinterpret_cast<float2*>(&out[(size_t)(r + 8) * N_TOTAL + c]) = v1;
            #pragma unroll
            for (int j = 0; j < 4; j++) {
                if (fabsf(z[j]) < TAU) {
                    const int rr = r + (j >> 1) * 8;
                    const int cc = c + (j & 1);
                    unsigned p = atomicAdd(s_cnt, 1u);
                    if (p < LCAP) {
                        s_idx[p] = (unsigned)rr * N_TOTAL + cc;
                        s_z[p]   = z[j];
                    }
                }
            }
        }
    }
    __syncthreads();

    // ---- inline fixup: warp-per-item exact lo-limb correction (from g_L) ----
    const unsigned total = min(*s_cnt, (unsigned)LCAP);
    for (unsigned it = wid; it < total; it += 8) {
        const unsigned idx = s_idx[it];
        const int m = idx >> 12;
        const int n = idx & (N_TOTAL - 1);
        const uint4* lr = reinterpret_cast<const uint4*>(g_L + (size_t)m * K_IN);
        const uint4* wr = reinterpret_cast<const uint4*>(g_W + (size_t)n * K_IN);
        float s = 0.f;
        #pragma unroll 4
        for (int i = 0; i < 16; i++) {
            const int ch = i * 32 + lane;
            uint4 lv = lr[ch];
            uint4 wv = wr[ch];
            const __half2* lh = reinterpret_cast<const __half2*>(&lv);
            const __half2* wh = reinterpret_cast<const __half2*>(&wv);
            #pragma unroll
            for (int q = 0; q < 4; q++) {
                float2 lf = __half22float2(lh[q]);
                float2 wf = __half22float2(wh[q]);
                s += lf.x * wf.x + lf.y * wf.y;
            }
        }
        #pragma unroll
        for (int o = 16; o; o >>= 1) s += __shfl_xor_sync(0xffffffffu, s, o);
        if (lane == 0) out[idx] = sgnf(s_z[it] + s);
    }
}

// ---------------- host launch ----------------
extern "C" void kernel_launch(void* const* d_in, const int* in_sizes, int n_in,
                              void* d_out, int out_size) {
    const float* x    = (const float*)d_in[0];
    const float* w    = (const float*)d_in[1];
    const float* bias = (const float*)d_in[2];
    float* out = (float*)d_out;

    const int nv = (int)((NX8 + NW8 + 255) / 256);
    prep_all<<<nv, 256>>>(x, w);

    cudaFuncSetAttribute(binlin_gemm, cudaFuncAttributeMaxDynamicSharedMemorySize,
                         SMEM_BYTES);
    binlin_gemm<<<dim3(N_TOTAL / BN, M_TOTAL / BM), 256, SMEM_BYTES>>>(bias, out);
}